// round 1
// baseline (speedup 1.0000x reference)
#include <cuda_runtime.h>
#include <cstdint>

// Problem constants
#define BATCH 32
#define TT 512
#define NINP 128
#define NHID 1024
#define KTOT (NINP + NHID)       // 1152 unified K
#define DT_C 0.042f
#define EPSH 512.0f               // HARMONIC = N_HID * 0.5

// Kernel geometry
#define NCTA 128
#define COLS 8                     // output columns per CTA
#define TPB 128                    // 4 warps
#define NW 4

#define BTH (BATCH * TT * NHID)    // 16777216 elements per output tensor

// ---- device scratch (static allocation: allowed) ----
__device__ float g_xT[TT * NINP * BATCH];     // [t][i][b]  8 MB
__device__ float g_hyT[2][NHID * BATCH];      // [parity][h][b]  2 x 128 KB
__device__ unsigned g_bar_arrive;
__device__ volatile unsigned g_bar_gen;

// ------------------------------------------------------------------
// init: reset barrier state + zero hy state buffer (parity 0)
// ------------------------------------------------------------------
__global__ void k_init() {
    int idx = blockIdx.x * blockDim.x + threadIdx.x;
    if (idx == 0) { g_bar_arrive = 0; g_bar_gen = 0; }
    int stride = gridDim.x * blockDim.x;
    for (int i = idx; i < NHID * BATCH; i += stride) g_hyT[0][i] = 0.0f;
}

// ------------------------------------------------------------------
// zero the u / spike output slabs (they are provably always zero)
// ------------------------------------------------------------------
__global__ void k_zero(float* __restrict__ p, int n4) {
    int idx = blockIdx.x * blockDim.x + threadIdx.x;
    int stride = gridDim.x * blockDim.x;
    float4 z = make_float4(0.f, 0.f, 0.f, 0.f);
    float4* p4 = reinterpret_cast<float4*>(p);
    for (int i = idx; i < n4; i += stride) p4[i] = z;
}

// ------------------------------------------------------------------
// transpose x[b][t][i] -> g_xT[t][i][b]   (coalesced writes)
// ------------------------------------------------------------------
__global__ void k_xpose(const float* __restrict__ x) {
    int idx = blockIdx.x * blockDim.x + threadIdx.x;
    int stride = gridDim.x * blockDim.x;
    const int N = TT * NINP * BATCH;
    for (int o = idx; o < N; o += stride) {
        int b = o & (BATCH - 1);
        int ti = o >> 5;              // t*NINP + i
        int i = ti & (NINP - 1);
        int t = ti >> 7;
        g_xT[o] = x[(size_t)b * (TT * NINP) + (size_t)t * NINP + i];
    }
}

// ------------------------------------------------------------------
// persistent recurrent kernel
// grid = 128 CTAs (co-resident), 128 threads each
// ------------------------------------------------------------------
__global__ void __launch_bounds__(TPB, 1) k_recur(
    const float* __restrict__ x2h,    // [NINP][NHID]
    const float* __restrict__ h2h,    // [NHID][NHID]
    const float* __restrict__ gamma,
    const float* __restrict__ eps,
    const float* __restrict__ bias,
    float* __restrict__ out)          // [4][B][T][H] (hy, hz, u, spk)
{
    __shared__ float w_s[COLS][KTOT];          // 36 KB, weight slice (k-major per col)
    __shared__ float red_s[NW][COLS][BATCH];   // 4 KB, cross-warp reduction

    const int tid  = threadIdx.x;
    const int wid  = tid >> 5;
    const int lane = tid & 31;
    const int cg0  = blockIdx.x * COLS;

    // --- load weight slice into SMEM: w_s[c][k] ---
    for (int idx = tid; idx < COLS * KTOT; idx += TPB) {
        int c = idx / KTOT;
        int k = idx - c * KTOT;
        float v = (k < NINP) ? x2h[(size_t)k * NHID + cg0 + c]
                             : h2h[(size_t)(k - NINP) * NHID + cg0 + c];
        w_s[c][k] = v;
    }

    // --- per-thread state: this thread owns (c = wid + 4*cc, b = lane), cc in {0,1}
    float hy_r[2] = {0.f, 0.f};
    float hz_r[2] = {0.f, 0.f};
    float gam[2], epc[2], bi[2];
#pragma unroll
    for (int cc = 0; cc < 2; cc++) {
        int hg = cg0 + wid + 4 * cc;
        gam[cc] = gamma[hg];
        epc[cc] = eps[hg] * EPSH;
        bi[cc]  = bias[hg];
    }

    __syncthreads();

    const int kb_x = wid * (NINP / NW);   // 32 x-rows per warp
    const int kb_h = wid * (NHID / NW);   // 256 hy-rows per warp
    const unsigned nblk = gridDim.x;

    for (int t = 0; t < TT; t++) {
        const int p = t & 1;
        const float* __restrict__ hyT = g_hyT[p];
        const float* __restrict__ xT  = g_xT + (size_t)t * (NINP * BATCH);

        float acc[COLS];
#pragma unroll
        for (int c = 0; c < COLS; c++) acc[c] = 0.f;

        // ---- x-part (K = 128, this warp's 32 rows) ----
#pragma unroll
        for (int kk = 0; kk < NINP / NW; kk += 8) {
            float hv[8];
#pragma unroll
            for (int j = 0; j < 8; j++)
                hv[j] = __ldg(&xT[(kb_x + kk + j) * BATCH + lane]);
#pragma unroll
            for (int c = 0; c < COLS; c++) {
                const float4* wr = reinterpret_cast<const float4*>(&w_s[c][kb_x + kk]);
                float4 w0 = wr[0], w1 = wr[1];
                float a = acc[c];
                a = fmaf(hv[0], w0.x, a); a = fmaf(hv[1], w0.y, a);
                a = fmaf(hv[2], w0.z, a); a = fmaf(hv[3], w0.w, a);
                a = fmaf(hv[4], w1.x, a); a = fmaf(hv[5], w1.y, a);
                a = fmaf(hv[6], w1.z, a); a = fmaf(hv[7], w1.w, a);
                acc[c] = a;
            }
        }

        // ---- hy-part (K = 1024, this warp's 256 rows) ----
#pragma unroll 4
        for (int kk = 0; kk < NHID / NW; kk += 8) {
            float hv[8];
#pragma unroll
            for (int j = 0; j < 8; j++)
                hv[j] = __ldcg(&hyT[(kb_h + kk + j) * BATCH + lane]);  // L1-bypass: coherent
#pragma unroll
            for (int c = 0; c < COLS; c++) {
                const float4* wr = reinterpret_cast<const float4*>(&w_s[c][NINP + kb_h + kk]);
                float4 w0 = wr[0], w1 = wr[1];
                float a = acc[c];
                a = fmaf(hv[0], w0.x, a); a = fmaf(hv[1], w0.y, a);
                a = fmaf(hv[2], w0.z, a); a = fmaf(hv[3], w0.w, a);
                a = fmaf(hv[4], w1.x, a); a = fmaf(hv[5], w1.y, a);
                a = fmaf(hv[6], w1.z, a); a = fmaf(hv[7], w1.w, a);
                acc[c] = a;
            }
        }

        // ---- cross-warp K reduction ----
#pragma unroll
        for (int c = 0; c < COLS; c++) red_s[wid][c][lane] = acc[c];
        __syncthreads();

        // ---- state update + output writes (each thread: 2 (c,b) pairs) ----
#pragma unroll
        for (int cc = 0; cc < 2; cc++) {
            const int c = wid + 4 * cc;
            float pre = bi[cc] + red_s[0][c][lane] + red_s[1][c][lane]
                                + red_s[2][c][lane] + red_s[3][c][lane];
            float drive = tanhf(pre);
            float hz = hz_r[cc], hy = hy_r[cc];
            hz += DT_C * (drive - gam[cc] * hy - epc[cc] * hz);
            hy += DT_C * hz;
            hz_r[cc] = hz; hy_r[cc] = hy;

            const int hg = cg0 + c;
            const size_t obase = (size_t)lane * (TT * NHID) + (size_t)t * NHID + hg;
            out[obase]       = hy;               // hy slab
            out[obase + BTH] = hz;               // hz slab
            __stcg(&g_hyT[p ^ 1][hg * BATCH + lane], hy);
        }

        // ---- grid barrier (sense-counting, one per step) ----
        __syncthreads();
        if (tid == 0) {
            __threadfence();
            unsigned a = atomicAdd(&g_bar_arrive, 1u);
            if (a == nblk - 1) {
                g_bar_arrive = 0;
                __threadfence();
                g_bar_gen = (unsigned)(t + 1);
            } else {
                while (g_bar_gen < (unsigned)(t + 1)) __nanosleep(64);
            }
            __threadfence();
        }
        __syncthreads();
    }
}

// ------------------------------------------------------------------
extern "C" void kernel_launch(void* const* d_in, const int* in_sizes, int n_in,
                              void* d_out, int out_size) {
    const float* x     = (const float*)d_in[0];
    const float* x2h   = (const float*)d_in[1];
    const float* h2h   = (const float*)d_in[2];
    const float* gamma = (const float*)d_in[3];
    const float* eps   = (const float*)d_in[4];
    const float* bias  = (const float*)d_in[5];
    float* out = (float*)d_out;

    // reset barrier + hy state
    k_init<<<64, 256>>>();
    // transpose x into [t][i][b]
    k_xpose<<<512, 256>>>(x);
    // u and spike outputs are identically zero (u is never driven from 0 init)
    k_zero<<<2048, 256>>>(out + (size_t)2 * BTH, (2 * BTH) / 4);
    // sequential recurrence
    k_recur<<<NCTA, TPB>>>(x2h, h2h, gamma, eps, bias, out);
}

// round 2
// speedup vs baseline: 1.2101x; 1.2101x over previous
#include <cuda_runtime.h>
#include <cstdint>

// Problem constants
#define BATCH 32
#define TT 512
#define NINP 128
#define NHID 1024
#define KTOT (NINP + NHID)        // 1152 unified K
#define DT_C 0.042f
#define EPSH 512.0f               // HARMONIC = N_HID * 0.5

// Geometry: 128 CTAs = 32 col-groups x 4 batch-groups
#define NCTA 128
#define COLS 32                   // output columns per CTA
#define BPC  8                    // batches per CTA
#define TPB  256                  // 8 warps
#define NW   8
#define KSL  (KTOT / NW)          // 144 K-rows per warp
#define WSTRIDE 1156              // padded weight row stride (floats), 16B-aligned,
                                  // phase-conflict-free for LDS.128

#define BTH (BATCH * TT * NHID)   // elements per output tensor

// SMEM layout (floats)
#define OFF_W    0
#define SZ_W     (COLS * WSTRIDE)             // 36992
#define OFF_IN   (OFF_W + SZ_W)               // in_s[k][8b]
#define SZ_IN    (KTOT * BPC)                 // 9216
#define OFF_RED  (OFF_IN + SZ_IN)             // red[w][b][c]
#define SZ_RED   (NW * BPC * COLS)            // 2048
#define OFF_HYST (OFF_RED + SZ_RED)           // hyst[c][b]
#define SZ_HYST  (COLS * BPC)                 // 256
#define SMEM_FLOATS (OFF_HYST + SZ_HYST)
#define SMEM_BYTES  (SMEM_FLOATS * 4)         // ~194 KB

// ---- device scratch ----
__device__ float g_xT[TT * NINP * BATCH];     // [t][i][b]
__device__ float g_hyT[2][NHID * BATCH];      // [parity][h][b]
__device__ unsigned g_bar_arrive;
__device__ volatile unsigned g_bar_gen;

// packed f32x2 FMA: acc = w2 * h2 + acc (elementwise, full fp32)
__device__ __forceinline__ void ffma2(unsigned long long& acc,
                                      unsigned long long w2,
                                      unsigned long long h2) {
    asm("fma.rn.f32x2 %0, %1, %2, %0;" : "+l"(acc) : "l"(w2), "l"(h2));
}
__device__ __forceinline__ unsigned long long pack2(float lo, float hi) {
    unsigned long long r;
    asm("mov.b64 %0, {%1, %2};" : "=l"(r) : "f"(lo), "f"(hi));
    return r;
}
__device__ __forceinline__ void unpack2(unsigned long long v, float& lo, float& hi) {
    asm("mov.b64 {%0, %1}, %2;" : "=f"(lo), "=f"(hi) : "l"(v));
}

// ------------------------------------------------------------------
__global__ void k_init() {
    int idx = blockIdx.x * blockDim.x + threadIdx.x;
    if (idx == 0) { g_bar_arrive = 0; g_bar_gen = 0; }
    int stride = gridDim.x * blockDim.x;
    for (int i = idx; i < NHID * BATCH; i += stride) g_hyT[0][i] = 0.0f;
}

__global__ void k_zero(float* __restrict__ p, int n4) {
    int idx = blockIdx.x * blockDim.x + threadIdx.x;
    int stride = gridDim.x * blockDim.x;
    float4 z = make_float4(0.f, 0.f, 0.f, 0.f);
    float4* p4 = reinterpret_cast<float4*>(p);
    for (int i = idx; i < n4; i += stride) p4[i] = z;
}

// transpose x[b][t][i] -> g_xT[t][i][b]
__global__ void k_xpose(const float* __restrict__ x) {
    int idx = blockIdx.x * blockDim.x + threadIdx.x;
    int stride = gridDim.x * blockDim.x;
    const int N = TT * NINP * BATCH;
    for (int o = idx; o < N; o += stride) {
        int b = o & (BATCH - 1);
        int ti = o >> 5;
        int i = ti & (NINP - 1);
        int t = ti >> 7;
        g_xT[o] = x[(size_t)b * (TT * NINP) + (size_t)t * NINP + i];
    }
}

// ------------------------------------------------------------------
// persistent recurrent kernel: 128 CTAs x 256 threads
// ------------------------------------------------------------------
__global__ void __launch_bounds__(TPB, 1) k_recur(
    const float* __restrict__ x2h,    // [NINP][NHID]
    const float* __restrict__ h2h,    // [NHID][NHID]
    const float* __restrict__ gamma,
    const float* __restrict__ eps,
    const float* __restrict__ bias,
    float* __restrict__ out)          // [4][B][T][H]
{
    extern __shared__ float sm[];
    float* w_s  = sm + OFF_W;     // [COLS][WSTRIDE] col-major rows of K
    float* in_s = sm + OFF_IN;    // [KTOT][BPC]
    float* red  = sm + OFF_RED;   // [NW][BPC][COLS]
    float* hyst = sm + OFF_HYST;  // [COLS][BPC]

    const int tid  = threadIdx.x;
    const int wid  = tid >> 5;
    const int lane = tid & 31;
    const int cgrp = blockIdx.x >> 2;        // 0..31
    const int bg   = blockIdx.x & 3;         // 0..3
    const int cg0  = cgrp * COLS;
    const int b0   = bg * BPC;

    // --- load weight slice: w_s[c][k] = W[k][cg0+c] ---
    for (int idx = tid; idx < COLS * KTOT; idx += TPB) {
        int k = idx >> 5;                     // 0..1151 (idx = k*32 + c, coalesced in c)
        int c = idx & 31;
        float v = (k < NINP) ? x2h[(size_t)k * NHID + cg0 + c]
                             : h2h[(size_t)(k - NINP) * NHID + cg0 + c];
        w_s[c * WSTRIDE + k] = v;
    }

    // --- per-thread state (update phase mapping: c = tid&31, b = tid>>5) ---
    const int uc = tid & 31;
    const int ub = tid >> 5;
    const int hg = cg0 + uc;
    float hy_r = 0.f, hz_r = 0.f;
    const float gam = gamma[hg];
    const float epc = eps[hg] * EPSH;
    const float bi  = bias[hg];

    // --- stage x slab for t = 0: in_s[k<128][b] ---
    {
        int row = tid >> 1, half = tid & 1;   // 128 rows x 2 halves
        float4 v = __ldg((const float4*)&g_xT[(size_t)0 + (size_t)row * BATCH + b0 + half * 4]);
        *(float4*)&in_s[row * BPC + half * 4] = v;
    }

    __syncthreads();

    const int kb = wid * KSL;                 // this warp's K base
    const unsigned nblk = gridDim.x;
    const float4* w4 = (const float4*)(w_s + (size_t)lane * WSTRIDE);

    for (int t = 0; t < TT; t++) {
        const int p = t & 1;

        // ---- stage hy rows into in_s[128+h][b] (coherent L2 loads) ----
        {
            const float* hyT = g_hyT[p];
#pragma unroll
            for (int i = 0; i < 8; i++) {
                int idx = tid + i * TPB;      // 0..2047
                int h = idx >> 1, half = idx & 1;
                float4 v = __ldcg((const float4*)&hyT[(size_t)h * BATCH + b0 + half * 4]);
                *(float4*)&in_s[(NINP + h) * BPC + half * 4] = v;
            }
        }
        __syncthreads();

        // ---- GEMM slice: warp covers K rows [kb, kb+144), lane = col ----
        unsigned long long acc2[4];
#pragma unroll
        for (int i = 0; i < 4; i++) acc2[i] = 0ull;

#pragma unroll 4
        for (int ch = 0; ch < KSL / 4; ch++) {
            const int k = kb + ch * 4;
            float4 wv = w4[k >> 2];
            const ulonglong2* hrow = (const ulonglong2*)(in_s + (size_t)k * BPC);
            float wa[4] = {wv.x, wv.y, wv.z, wv.w};
#pragma unroll
            for (int j = 0; j < 4; j++) {
                ulonglong2 ha = hrow[2 * j];      // batches 0..3 of row k+j
                ulonglong2 hb = hrow[2 * j + 1];  // batches 4..7
                unsigned long long w2 = pack2(wa[j], wa[j]);
                ffma2(acc2[0], w2, ha.x);
                ffma2(acc2[1], w2, ha.y);
                ffma2(acc2[2], w2, hb.x);
                ffma2(acc2[3], w2, hb.y);
            }
        }

        // ---- write partials: red[wid][b][lane] ----
#pragma unroll
        for (int i = 0; i < 4; i++) {
            float lo, hi;
            unpack2(acc2[i], lo, hi);
            red[(wid * BPC + 2 * i) * COLS + lane]     = lo;
            red[(wid * BPC + 2 * i + 1) * COLS + lane] = hi;
        }
        __syncthreads();

        // ---- update phase: thread owns (uc, ub) ----
        {
            float pre = bi;
#pragma unroll
            for (int w = 0; w < NW; w++)
                pre += red[(w * BPC + ub) * COLS + uc];
            float drive = tanhf(pre);
            hz_r += DT_C * (drive - gam * hy_r - epc * hz_r);
            hy_r += DT_C * hz_r;

            const size_t obase = (size_t)(b0 + ub) * (TT * NHID) + (size_t)t * NHID + hg;
            out[obase]       = hy_r;
            out[obase + BTH] = hz_r;
            hyst[uc * BPC + ub] = hy_r;
        }

        // ---- prefetch next x slab (doesn't depend on other CTAs) ----
        if (t + 1 < TT) {
            int row = tid >> 1, half = tid & 1;
            float4 v = __ldg((const float4*)&g_xT[(size_t)(t + 1) * (NINP * BATCH)
                                                  + (size_t)row * BATCH + b0 + half * 4]);
            __syncthreads();                  // hyst complete + compute done before overwrite
            *(float4*)&in_s[row * BPC + half * 4] = v;
        } else {
            __syncthreads();
        }

        // ---- transposed hy writeback: 32B-aligned chunks ----
        {
            int c2 = tid >> 3, b2 = tid & 7;
            __stcg(&g_hyT[p ^ 1][(size_t)(cg0 + c2) * BATCH + b0 + b2], hyst[tid]);
        }

        // ---- grid barrier ----
        __syncthreads();
        if (tid == 0) {
            __threadfence();
            unsigned a = atomicAdd(&g_bar_arrive, 1u);
            if (a == nblk - 1) {
                g_bar_arrive = 0;
                __threadfence();
                g_bar_gen = (unsigned)(t + 1);
            } else {
                while (g_bar_gen < (unsigned)(t + 1)) __nanosleep(32);
            }
            __threadfence();
        }
        __syncthreads();
    }
}

// ------------------------------------------------------------------
extern "C" void kernel_launch(void* const* d_in, const int* in_sizes, int n_in,
                              void* d_out, int out_size) {
    const float* x     = (const float*)d_in[0];
    const float* x2h   = (const float*)d_in[1];
    const float* h2h   = (const float*)d_in[2];
    const float* gamma = (const float*)d_in[3];
    const float* eps   = (const float*)d_in[4];
    const float* bias  = (const float*)d_in[5];
    float* out = (float*)d_out;

    static bool attr_set = false;
    if (!attr_set) {
        cudaFuncSetAttribute(k_recur, cudaFuncAttributeMaxDynamicSharedMemorySize, SMEM_BYTES);
        attr_set = true;
    }

    k_init<<<64, 256>>>();
    k_xpose<<<512, 256>>>(x);
    // u and spike outputs are identically zero (u is never driven from 0 init)
    k_zero<<<2048, 256>>>(out + (size_t)2 * BTH, (2 * BTH) / 4);
    k_recur<<<NCTA, TPB, SMEM_BYTES>>>(x2h, h2h, gamma, eps, bias, out);
}